// round 9
// baseline (speedup 1.0000x reference)
#include <cuda_runtime.h>

#define NN 100000
#define EMAX 3200000

// ---- scratch (no allocations allowed; __device__ globals) ----
__device__ int   g_deg[NN];
__device__ float g_dis[NN];
__device__ int   g_rowstart[NN + 1];
__device__ int   g_cursor[NN];
__device__ int   g_srcs[EMAX];
__device__ __align__(16) float g_hs1[NN * 32];   // dis-scaled x@W1^T
__device__ __align__(16) float g_y1 [NN * 32];   // relu(layer1)
__device__ __align__(16) float g_hs2[NN * 16];   // dis-scaled y1@W2^T
__device__ int   g_bsum[256];
__device__ int   g_is64;

// ---------------- edge-index dtype detection ----------------
// jnp.int64 demotes to int32 unless x64 is enabled; element counts are
// identical either way (6.4M), so sniff the payload: true int64 values
// < 100000 have all-zero high words (odd int32 slots); int32 data has
// random node ids there.
__global__ void k_detect(const int* __restrict__ ei32) {
    if (threadIdx.x == 0) {
        int any = 0;
        for (int i = 1; i < 64; i += 2) any |= ei32[i];
        g_is64 = (any == 0) ? 1 : 0;
    }
}

__device__ __forceinline__ int edge_src(const void* ei, int E, int e) {
    return g_is64 ? (int)((const long long*)ei)[e] : ((const int*)ei)[e];
}
__device__ __forceinline__ int edge_dst(const void* ei, int E, int e) {
    return g_is64 ? (int)((const long long*)ei)[E + e] : ((const int*)ei)[E + e];
}

// ---------------- CSR build ----------------
__global__ void k_init() {
    int i = blockIdx.x * blockDim.x + threadIdx.x;
    if (i < NN) { g_deg[i] = 1; g_cursor[i] = 0; }   // self-loop counts toward degree
}

__global__ void k_count(const void* __restrict__ ei, int E) {
    int e = blockIdx.x * blockDim.x + threadIdx.x;
    if (e < E) {
        int d = edge_dst(ei, E, e);
        if ((unsigned)d < NN) atomicAdd(&g_deg[d], 1);   // guard: misdetect -> wrong, not crash
    }
}

// block-wide exclusive scan of edge counts (deg-1); also dis = rsqrt(deg)
__global__ void k_scan1() {
    __shared__ int sh[1024];
    int t = threadIdx.x;
    int i = blockIdx.x * 1024 + t;
    int v = (i < NN) ? (g_deg[i] - 1) : 0;
    if (i < NN) g_dis[i] = rsqrtf((float)g_deg[i]);
    sh[t] = v;
    __syncthreads();
    for (int off = 1; off < 1024; off <<= 1) {
        int x = (t >= off) ? sh[t - off] : 0;
        __syncthreads();
        sh[t] += x;
        __syncthreads();
    }
    if (i < NN) g_rowstart[i] = sh[t] - v;       // exclusive
    if (t == 1023) g_bsum[blockIdx.x] = sh[1023];
}

__global__ void k_scan2(int nb) {
    if (threadIdx.x == 0) {
        int run = 0;
        for (int b = 0; b < nb; b++) { int s = g_bsum[b]; g_bsum[b] = run; run += s; }
    }
}

__global__ void k_scan3(int E) {
    int i = blockIdx.x * blockDim.x + threadIdx.x;
    if (i < NN) g_rowstart[i] += g_bsum[i >> 10];
    if (i == NN) g_rowstart[NN] = E;
}

__global__ void k_fill(const void* __restrict__ ei, int E) {
    int e = blockIdx.x * blockDim.x + threadIdx.x;
    if (e < E) {
        int d = edge_dst(ei, E, e);
        if ((unsigned)d < NN) {
            int pos = g_rowstart[d] + atomicAdd(&g_cursor[d], 1);
            int s = edge_src(ei, E, e);
            g_srcs[pos] = ((unsigned)s < NN) ? s : 0;
        }
    }
}

// ---------------- layer 1 transform: hs1 = dis[n] * (x[n] @ W1^T) ----------------
__global__ void k_gemm1(const float* __restrict__ x, const float* __restrict__ W1) {
    __shared__ float4 sW[32 * 32];                 // W1 [32,128] as float4
    for (int i = threadIdx.x; i < 1024; i += blockDim.x)
        sW[i] = ((const float4*)W1)[i];
    __syncthreads();
    int n = blockIdx.x * blockDim.x + threadIdx.x;
    if (n >= NN) return;
    float acc[32];
#pragma unroll
    for (int j = 0; j < 32; j++) acc[j] = 0.f;
    const float4* xr = (const float4*)(x + (size_t)n * 128);
#pragma unroll 8
    for (int k4 = 0; k4 < 32; k4++) {
        float4 xv = xr[k4];
#pragma unroll
        for (int j = 0; j < 32; j++) {
            float4 w = sW[j * 32 + k4];
            acc[j] += xv.x * w.x + xv.y * w.y + xv.z * w.z + xv.w * w.w;
        }
    }
    float dv = g_dis[n];
    float4* o = (float4*)(g_hs1 + (size_t)n * 32);
#pragma unroll
    for (int j = 0; j < 8; j++)
        o[j] = make_float4(acc[4*j] * dv, acc[4*j+1] * dv, acc[4*j+2] * dv, acc[4*j+3] * dv);
}

// ---------------- layer 1 aggregate: warp per node, 32 lanes = 32 feats ----------------
__global__ void k_agg1(const float* __restrict__ b1) {
    int gt = blockIdx.x * blockDim.x + threadIdx.x;
    int v = gt >> 5, lane = threadIdx.x & 31;
    if (v >= NN) return;
    float acc = g_hs1[v * 32 + lane];              // self-loop term (already dis-scaled)
    int s0 = g_rowstart[v], s1 = g_rowstart[v + 1];
    for (int base = s0; base < s1; base += 32) {
        int idx = base + lane;
        int sv = g_srcs[idx < s1 ? idx : s1 - 1];
        int cnt = s1 - base;
        if (cnt >= 32) {
#pragma unroll
            for (int j = 0; j < 32; j++) {
                int s = __shfl_sync(0xffffffffu, sv, j);
                acc += g_hs1[s * 32 + lane];       // coalesced 128B line / edge
            }
        } else {
            for (int j = 0; j < cnt; j++) {
                int s = __shfl_sync(0xffffffffu, sv, j);
                acc += g_hs1[s * 32 + lane];
            }
        }
    }
    float r = g_dis[v] * acc + b1[lane];
    g_y1[v * 32 + lane] = fmaxf(r, 0.f);
}

// ---------------- layer 2 transform: hs2 = dis[n] * (y1[n] @ W2^T) ----------------
__global__ void k_gemm2(const float* __restrict__ W2) {
    __shared__ float sW[512];                      // W2 [16,32]
    for (int i = threadIdx.x; i < 512; i += blockDim.x) sW[i] = W2[i];
    __syncthreads();
    int n = blockIdx.x * blockDim.x + threadIdx.x;
    if (n >= NN) return;
    float xin[32];
    const float4* yr = (const float4*)(g_y1 + (size_t)n * 32);
#pragma unroll
    for (int k4 = 0; k4 < 8; k4++) {
        float4 t = yr[k4];
        xin[4*k4] = t.x; xin[4*k4+1] = t.y; xin[4*k4+2] = t.z; xin[4*k4+3] = t.w;
    }
    float dv = g_dis[n];
#pragma unroll
    for (int j = 0; j < 16; j++) {
        float a = 0.f;
#pragma unroll
        for (int k = 0; k < 32; k++) a += xin[k] * sW[j * 32 + k];
        g_hs2[n * 16 + j] = a * dv;
    }
}

// ---------------- layer 2 aggregate + fused LSTM + output proj ----------------
// 16 lanes per node; two nodes per warp. y2 never hits memory.
__global__ void k_agg2(const float* __restrict__ b2, const float* __restrict__ w_ih,
                       const float* __restrict__ b_ih, const float* __restrict__ b_hh,
                       const float* __restrict__ W_out, const float* __restrict__ b_out,
                       float* __restrict__ out) {
    int gt = blockIdx.x * blockDim.x + threadIdx.x;
    int v = gt >> 4;
    int lane = threadIdx.x & 31;
    int gl = lane & 15;
    unsigned gmask = 0xFFFFu << (lane & 16);       // own half-warp only (groups may diverge)
    if (v >= NN) return;

    float acc = g_hs2[v * 16 + gl];                // self-loop
    int s0 = g_rowstart[v], s1 = g_rowstart[v + 1];
    for (int base = s0; base < s1; base += 16) {
        int idx = base + gl;
        int sv = g_srcs[idx < s1 ? idx : s1 - 1];
        int cnt = s1 - base;
        if (cnt >= 16) {
#pragma unroll
            for (int j = 0; j < 16; j++) {
                int s = __shfl_sync(gmask, sv, j, 16);
                acc += g_hs2[s * 16 + gl];
            }
        } else {
            for (int j = 0; j < cnt; j++) {
                int s = __shfl_sync(gmask, sv, j, 16);
                acc += g_hs2[s * 16 + gl];
            }
        }
    }
    float y2 = fmaxf(g_dis[v] * acc + b2[gl], 0.f);

    // LSTM (h0=c0=0): gates i,g,o only (f multiplies c0=0; w_hh term zero).
    // All 16 lanes compute (lanes 8-15 duplicate j = gl&7 to stay converged).
    int j = gl & 7;
    float ai = b_ih[j]      + b_hh[j];
    float ag = b_ih[16 + j] + b_hh[16 + j];
    float ao = b_ih[24 + j] + b_hh[24 + j];
#pragma unroll
    for (int k = 0; k < 16; k++) {
        float vv = __shfl_sync(gmask, y2, k, 16);
        ai += w_ih[j * 16 + k]        * vv;
        ag += w_ih[(16 + j) * 16 + k] * vv;
        ao += w_ih[(24 + j) * 16 + k] * vv;
    }
    float c  = (1.f / (1.f + __expf(-ai))) * tanhf(ag);
    float hh = (1.f / (1.f + __expf(-ao))) * tanhf(c);
    float part = (gl < 8) ? hh * W_out[j] : 0.f;
#pragma unroll
    for (int off = 8; off; off >>= 1)
        part += __shfl_xor_sync(gmask, part, off, 16);
    if (gl == 0) out[v] = part + b_out[0];
}

// ---------------- launch ----------------
extern "C" void kernel_launch(void* const* d_in, const int* in_sizes, int n_in,
                              void* d_out, int out_size) {
    const float* x     = (const float*)d_in[0];
    const void*  ei    = d_in[1];
    const float* W1    = (const float*)d_in[2];
    const float* b1    = (const float*)d_in[3];
    const float* W2    = (const float*)d_in[4];
    const float* b2    = (const float*)d_in[5];
    const float* w_ih  = (const float*)d_in[6];
    // d_in[7] = w_hh: unused (h0 == 0)
    const float* b_ih  = (const float*)d_in[8];
    const float* b_hh  = (const float*)d_in[9];
    const float* W_out = (const float*)d_in[10];
    const float* b_out = (const float*)d_in[11];
    float*       out   = (float*)d_out;

    int E  = in_sizes[1] / 2;   // element count is 6.4M for both int32 and int64
    int nb = (NN + 1023) / 1024;

    k_detect<<<1, 32>>>((const int*)ei);
    k_init  <<<(NN + 255) / 256, 256>>>();
    k_count <<<(E + 255) / 256, 256>>>(ei, E);
    k_scan1 <<<nb, 1024>>>();
    k_scan2 <<<1, 32>>>(nb);
    k_scan3 <<<(NN + 1 + 255) / 256, 256>>>(E);
    k_fill  <<<(E + 255) / 256, 256>>>(ei, E);
    k_gemm1 <<<(NN + 127) / 128, 128>>>(x, W1);
    k_agg1  <<<(NN * 32) / 256, 256>>>(b1);
    k_gemm2 <<<(NN + 255) / 256, 256>>>(W2);
    k_agg2  <<<(NN * 16) / 256, 256>>>(b2, w_ih, b_ih, b_hh, W_out, b_out, out);
}